// round 1
// baseline (speedup 1.0000x reference)
#include <cuda_runtime.h>

#define N_USERS 100000
#define N_ITEMS 200000
#define N_NODES (N_USERS + N_ITEMS)
#define DIM 256
#define DIM4 (DIM / 4)
#define N_EDGES 1000000
#define NDIR (2 * N_EDGES)
#define BATCH 8192
#define SCAN_BLK 1024
#define SCAN_NB ((N_NODES + SCAN_BLK - 1) / SCAN_BLK)   // 293

// ---------------- device scratch (static: allowed) ----------------
__device__ float g_x[(size_t)N_NODES * DIM];     // 307 MB
__device__ float g_y[(size_t)N_NODES * DIM];     // 307 MB
__device__ float g_acc[(size_t)N_NODES * DIM];   // 307 MB
__device__ int   g_deg[N_NODES];
__device__ int   g_rowptr[N_NODES + 1];
__device__ int   g_cursor[N_NODES];
__device__ float g_dinv[N_NODES];
__device__ int   g_csrsrc[NDIR];                 // 8 MB
__device__ int   g_part[SCAN_BLK];

// ---------------- graph preprocessing ----------------
__global__ void k_zero_deg() {
    int i = blockIdx.x * blockDim.x + threadIdx.x;
    if (i < N_NODES) g_deg[i] = 0;
}

__global__ void k_count_deg(const int* __restrict__ erow, const int* __restrict__ ecol) {
    int e = blockIdx.x * blockDim.x + threadIdx.x;
    if (e < N_EDGES) {
        atomicAdd(&g_deg[erow[e]], 1);
        atomicAdd(&g_deg[N_USERS + ecol[e]], 1);
    }
}

// phase 1: per-block inclusive scan -> exclusive within block + block totals
__global__ void k_scan1() {
    __shared__ int s[SCAN_BLK];
    int tid = threadIdx.x;
    int i = blockIdx.x * SCAN_BLK + tid;
    int v = (i < N_NODES) ? g_deg[i] : 0;
    s[tid] = v;
    __syncthreads();
    for (int off = 1; off < SCAN_BLK; off <<= 1) {
        int t = (tid >= off) ? s[tid - off] : 0;
        __syncthreads();
        s[tid] += t;
        __syncthreads();
    }
    if (i < N_NODES) g_rowptr[i] = s[tid] - v;          // exclusive within block
    if (tid == SCAN_BLK - 1) g_part[blockIdx.x] = s[tid];
}

// phase 2: scan block totals (SCAN_NB <= 512) in one block
__global__ void k_scan2() {
    __shared__ int s[512];
    int tid = threadIdx.x;
    int v = (tid < SCAN_NB) ? g_part[tid] : 0;
    s[tid] = v;
    __syncthreads();
    for (int off = 1; off < 512; off <<= 1) {
        int t = (tid >= off) ? s[tid - off] : 0;
        __syncthreads();
        s[tid] += t;
        __syncthreads();
    }
    if (tid < SCAN_NB) g_part[tid] = s[tid] - v;         // exclusive block offsets
}

// phase 3: add offsets, init cursor, compute dinv
__global__ void k_scan3() {
    int i = blockIdx.x * blockDim.x + threadIdx.x;
    if (i < N_NODES) {
        int rp = g_rowptr[i] + g_part[i / SCAN_BLK];
        g_rowptr[i] = rp;
        g_cursor[i] = rp;
        int d = g_deg[i];
        float df = (float)(d < 1 ? 1 : d);
        g_dinv[i] = rsqrtf(df);
    }
    if (i == 0) g_rowptr[N_NODES] = NDIR;
}

__global__ void k_scatter(const int* __restrict__ erow, const int* __restrict__ ecol) {
    int e = blockIdx.x * blockDim.x + threadIdx.x;
    if (e < N_EDGES) {
        int u = erow[e];
        int it = N_USERS + ecol[e];
        int p = atomicAdd(&g_cursor[u], 1);
        g_csrsrc[p] = it;
        int q = atomicAdd(&g_cursor[it], 1);
        g_csrsrc[q] = u;
    }
}

// ---------------- embedding init: x = acc = concat(user_emb, item_emb) ----------------
__global__ void k_init_x(const float* __restrict__ uemb, const float* __restrict__ iemb) {
    size_t i = (size_t)blockIdx.x * blockDim.x + threadIdx.x;
    size_t total = (size_t)N_NODES * DIM;
    if (i < total) {
        float v = (i < (size_t)N_USERS * DIM) ? uemb[i] : iemb[i - (size_t)N_USERS * DIM];
        g_x[i] = v;
        g_acc[i] = v;
    }
}

// ---------------- propagation layer: gather-sum over CSR, fused acc += ----------------
// 256 threads per block = 4 groups of 64 lanes; one dst row per group (float4 per lane).
__global__ void k_spmm(int flip) {
    const float4* __restrict__ xin = (const float4*)(flip ? g_y : g_x);
    float4* __restrict__ xout = (float4*)(flip ? g_x : g_y);
    float4* __restrict__ acc4 = (float4*)g_acc;

    int row = blockIdx.x * 4 + (threadIdx.x >> 6);
    int lane = threadIdx.x & 63;
    if (row >= N_NODES) return;

    int beg = g_rowptr[row];
    int end = g_rowptr[row + 1];
    float di = g_dinv[row];

    float4 sum = make_float4(0.f, 0.f, 0.f, 0.f);
    for (int e = beg; e < end; e++) {
        int s = g_csrsrc[e];
        float w = di * g_dinv[s];
        float4 v = xin[(size_t)s * DIM4 + lane];
        sum.x += w * v.x;
        sum.y += w * v.y;
        sum.z += w * v.z;
        sum.w += w * v.w;
    }
    size_t o = (size_t)row * DIM4 + lane;
    xout[o] = sum;
    float4 a = acc4[o];
    a.x += sum.x; a.y += sum.y; a.z += sum.z; a.w += sum.w;
    acc4[o] = a;
}

// ---------------- finalize: dots on acc/4 + raw embedding gathers ----------------
// one warp per batch element; 8 warps / block
__global__ void k_finalize(const int* __restrict__ uidx, const int* __restrict__ pidx,
                           const int* __restrict__ nidx,
                           const float* __restrict__ uemb, const float* __restrict__ iemb,
                           float* __restrict__ out) {
    int b = blockIdx.x * 8 + (threadIdx.x >> 5);
    int lane = threadIdx.x & 31;
    if (b >= BATCH) return;

    int u = uidx[b];
    int p = pidx[b];
    int n = nidx[b];

    const float* au = g_acc + (size_t)u * DIM;
    const float* ap = g_acc + (size_t)(N_USERS + p) * DIM;
    const float* an = g_acc + (size_t)(N_USERS + n) * DIM;

    float ps = 0.f, ns = 0.f;
#pragma unroll
    for (int d = lane; d < DIM; d += 32) {
        float ue = au[d];
        ps += ue * ap[d];
        ns += ue * an[d];
    }
#pragma unroll
    for (int off = 16; off > 0; off >>= 1) {
        ps += __shfl_down_sync(0xFFFFFFFFu, ps, off);
        ns += __shfl_down_sync(0xFFFFFFFFu, ns, off);
    }
    const float inv2 = 1.0f / ((1.f + 3.f) * (1.f + 3.f));   // (1/4)^2 applied to dot
    if (lane == 0) {
        out[b] = ps * inv2;
        out[BATCH + b] = ns * inv2;
    }

    float* oue = out + 2 * BATCH + (size_t)b * DIM;
    float* ope = out + 2 * BATCH + (size_t)BATCH * DIM + (size_t)b * DIM;
    float* one_ = out + 2 * BATCH + (size_t)2 * BATCH * DIM + (size_t)b * DIM;
    const float* su = uemb + (size_t)u * DIM;
    const float* sp = iemb + (size_t)p * DIM;
    const float* sn = iemb + (size_t)n * DIM;
#pragma unroll
    for (int d = lane; d < DIM; d += 32) {
        oue[d] = su[d];
        ope[d] = sp[d];
        one_[d] = sn[d];
    }
}

// ---------------- launch ----------------
extern "C" void kernel_launch(void* const* d_in, const int* in_sizes, int n_in,
                              void* d_out, int out_size) {
    const float* user_emb = (const float*)d_in[0];
    const float* item_emb = (const float*)d_in[1];
    const int* edge_row = (const int*)d_in[2];
    const int* edge_col = (const int*)d_in[3];
    const int* users_idx = (const int*)d_in[4];
    const int* pos_idx = (const int*)d_in[5];
    const int* neg_idx = (const int*)d_in[6];
    float* out = (float*)d_out;

    // graph build
    k_zero_deg<<<(N_NODES + 255) / 256, 256>>>();
    k_count_deg<<<(N_EDGES + 255) / 256, 256>>>(edge_row, edge_col);
    k_scan1<<<SCAN_NB, SCAN_BLK>>>();
    k_scan2<<<1, 512>>>();
    k_scan3<<<(N_NODES + 255) / 256, 256>>>();
    k_scatter<<<(N_EDGES + 255) / 256, 256>>>(edge_row, edge_col);

    // embedding init
    {
        size_t total = (size_t)N_NODES * DIM;
        k_init_x<<<(int)((total + 255) / 256), 256>>>(user_emb, item_emb);
    }

    // 3 propagation layers, ping-pong g_x <-> g_y
    int spmm_blocks = (N_NODES + 3) / 4;
    k_spmm<<<spmm_blocks, 256>>>(0);   // g_x -> g_y
    k_spmm<<<spmm_blocks, 256>>>(1);   // g_y -> g_x
    k_spmm<<<spmm_blocks, 256>>>(0);   // g_x -> g_y

    // outputs
    k_finalize<<<BATCH / 8, 256>>>(users_idx, pos_idx, neg_idx, user_emb, item_emb, out);
}

// round 2
// speedup vs baseline: 1.7505x; 1.7505x over previous
#include <cuda_runtime.h>

#define N_USERS 100000
#define N_ITEMS 200000
#define N_NODES (N_USERS + N_ITEMS)
#define DIM 256
#define DIM4 (DIM / 4)
#define N_EDGES 1000000
#define NDIR (2 * N_EDGES)
#define BATCH 8192
#define SCAN_BLK 1024
#define SCAN_NB ((N_NODES + SCAN_BLK - 1) / SCAN_BLK)   // 293

// ---------------- device scratch (static: allowed) ----------------
// propagating buffers store p_l = dinv * x_l  (pre-scaled)
__device__ float g_p0[(size_t)N_NODES * DIM];    // 307 MB
__device__ float g_p1[(size_t)N_NODES * DIM];    // 307 MB
__device__ float g_p2[(size_t)N_NODES * DIM];    // 307 MB
__device__ float g_x3c[(size_t)3 * BATCH * DIM]; // 25 MB, UNscaled x3 at finalize rows
__device__ int   g_deg[N_NODES];
__device__ int   g_rowptr[N_NODES + 1];
__device__ int   g_cursor[N_NODES];
__device__ float g_dinv[N_NODES];                // deg^-1/2
__device__ float g_rdeg[N_NODES];                // deg^+1/2 (un-scale factor)
__device__ int   g_csrsrc[NDIR];                 // 8 MB
__device__ int   g_part[SCAN_BLK];

// ---------------- graph preprocessing ----------------
__global__ void k_zero_deg() {
    int i = blockIdx.x * blockDim.x + threadIdx.x;
    if (i < N_NODES) g_deg[i] = 0;
}

__global__ void k_count_deg(const int* __restrict__ erow, const int* __restrict__ ecol) {
    int e = blockIdx.x * blockDim.x + threadIdx.x;
    if (e < N_EDGES) {
        atomicAdd(&g_deg[erow[e]], 1);
        atomicAdd(&g_deg[N_USERS + ecol[e]], 1);
    }
}

__global__ void k_scan1() {
    __shared__ int s[SCAN_BLK];
    int tid = threadIdx.x;
    int i = blockIdx.x * SCAN_BLK + tid;
    int v = (i < N_NODES) ? g_deg[i] : 0;
    s[tid] = v;
    __syncthreads();
    for (int off = 1; off < SCAN_BLK; off <<= 1) {
        int t = (tid >= off) ? s[tid - off] : 0;
        __syncthreads();
        s[tid] += t;
        __syncthreads();
    }
    if (i < N_NODES) g_rowptr[i] = s[tid] - v;
    if (tid == SCAN_BLK - 1) g_part[blockIdx.x] = s[tid];
}

__global__ void k_scan2() {
    __shared__ int s[512];
    int tid = threadIdx.x;
    int v = (tid < SCAN_NB) ? g_part[tid] : 0;
    s[tid] = v;
    __syncthreads();
    for (int off = 1; off < 512; off <<= 1) {
        int t = (tid >= off) ? s[tid - off] : 0;
        __syncthreads();
        s[tid] += t;
        __syncthreads();
    }
    if (tid < SCAN_NB) g_part[tid] = s[tid] - v;
}

__global__ void k_scan3() {
    int i = blockIdx.x * blockDim.x + threadIdx.x;
    if (i < N_NODES) {
        int rp = g_rowptr[i] + g_part[i / SCAN_BLK];
        g_rowptr[i] = rp;
        g_cursor[i] = rp;
        int d = g_deg[i];
        float df = (float)(d < 1 ? 1 : d);
        g_dinv[i] = rsqrtf(df);
        g_rdeg[i] = sqrtf(df);
    }
    if (i == 0) g_rowptr[N_NODES] = NDIR;
}

__global__ void k_scatter(const int* __restrict__ erow, const int* __restrict__ ecol) {
    int e = blockIdx.x * blockDim.x + threadIdx.x;
    if (e < N_EDGES) {
        int u = erow[e];
        int it = N_USERS + ecol[e];
        int p = atomicAdd(&g_cursor[u], 1);
        g_csrsrc[p] = it;
        int q = atomicAdd(&g_cursor[it], 1);
        g_csrsrc[q] = u;
    }
}

// ---------------- init: p0 = dinv * concat(user_emb, item_emb) ----------------
__global__ void k_init_p0(const float* __restrict__ uemb, const float* __restrict__ iemb) {
    size_t i = (size_t)blockIdx.x * blockDim.x + threadIdx.x;
    size_t total = (size_t)N_NODES * DIM;
    if (i < total) {
        size_t row = i >> 8; // /DIM
        float v = (i < (size_t)N_USERS * DIM) ? uemb[i] : iemb[i - (size_t)N_USERS * DIM];
        g_p0[i] = v * g_dinv[row];
    }
}

// ---------------- full propagation: p_out[dst] = dinv[dst]^2 * sum_src p_in[src] ----------
// 256 threads per block = 4 groups of 64 lanes; one dst row per group (float4 per lane).
__global__ void k_spmm_full(int which) {
    const float4* __restrict__ xin = (const float4*)(which == 0 ? g_p0 : g_p1);
    float4* __restrict__ xout = (float4*)(which == 0 ? g_p1 : g_p2);

    int row = blockIdx.x * 4 + (threadIdx.x >> 6);
    int lane = threadIdx.x & 63;
    if (row >= N_NODES) return;

    int beg = g_rowptr[row];
    int end = g_rowptr[row + 1];
    float di = g_dinv[row];
    float w = di * di;

    float4 sum = make_float4(0.f, 0.f, 0.f, 0.f);
    for (int e = beg; e < end; e++) {
        int s = g_csrsrc[e];
        float4 v = xin[(size_t)s * DIM4 + lane];
        sum.x += v.x;
        sum.y += v.y;
        sum.z += v.z;
        sum.w += v.w;
    }
    sum.x *= w; sum.y *= w; sum.z *= w; sum.w *= w;
    xout[(size_t)row * DIM4 + lane] = sum;
}

// ---------------- sparse layer 3: only at finalize rows; output UNscaled x3 ------------
__global__ void k_spmm_sparse(const int* __restrict__ uidx, const int* __restrict__ pidx,
                              const int* __restrict__ nidx) {
    int j = blockIdx.x * 4 + (threadIdx.x >> 6);
    int lane = threadIdx.x & 63;
    if (j >= 3 * BATCH) return;

    int node;
    if (j < BATCH) node = uidx[j];
    else if (j < 2 * BATCH) node = N_USERS + pidx[j - BATCH];
    else node = N_USERS + nidx[j - 2 * BATCH];

    int beg = g_rowptr[node];
    int end = g_rowptr[node + 1];
    float di = g_dinv[node];

    const float4* __restrict__ xin = (const float4*)g_p2;
    float4 sum = make_float4(0.f, 0.f, 0.f, 0.f);
    for (int e = beg; e < end; e++) {
        int s = g_csrsrc[e];
        float4 v = xin[(size_t)s * DIM4 + lane];
        sum.x += v.x;
        sum.y += v.y;
        sum.z += v.z;
        sum.w += v.w;
    }
    // x3 = dinv * sum(p2)
    sum.x *= di; sum.y *= di; sum.z *= di; sum.w *= di;
    ((float4*)g_x3c)[(size_t)j * DIM4 + lane] = sum;
}

// ---------------- finalize: acc = x0 + (p1+p2)*rdeg + x3 ; dots + raw gathers ----------
// one warp per batch element; 8 warps / block; float4 lanes (2 iters over DIM4=64)
__global__ void k_finalize(const int* __restrict__ uidx, const int* __restrict__ pidx,
                           const int* __restrict__ nidx,
                           const float* __restrict__ uemb, const float* __restrict__ iemb,
                           float* __restrict__ out) {
    int b = blockIdx.x * 8 + (threadIdx.x >> 5);
    int lane = threadIdx.x & 31;
    if (b >= BATCH) return;

    int u = uidx[b];
    int pi = pidx[b];
    int ni = nidx[b];
    int pn = N_USERS + pi;
    int nn = N_USERS + ni;

    float ru_ = g_rdeg[u], rp_ = g_rdeg[pn], rn_ = g_rdeg[nn];

    const float4* uemb4 = (const float4*)uemb;
    const float4* iemb4 = (const float4*)iemb;
    const float4* p14 = (const float4*)g_p1;
    const float4* p24 = (const float4*)g_p2;
    const float4* x3c4 = (const float4*)g_x3c;

    float4* oue = (float4*)(out + 2 * BATCH) + (size_t)b * DIM4;
    float4* ope = (float4*)(out + 2 * BATCH + (size_t)BATCH * DIM) + (size_t)b * DIM4;
    float4* one_ = (float4*)(out + 2 * BATCH + (size_t)2 * BATCH * DIM) + (size_t)b * DIM4;

    float ps = 0.f, ns = 0.f;
#pragma unroll
    for (int k = 0; k < 2; k++) {
        int d = lane + 32 * k;          // float4 index in [0,64)
        // user acc
        float4 r0 = uemb4[(size_t)u * DIM4 + d];
        float4 a1 = p14[(size_t)u * DIM4 + d];
        float4 a2 = p24[(size_t)u * DIM4 + d];
        float4 a3 = x3c4[(size_t)b * DIM4 + d];
        float4 au;
        au.x = r0.x + (a1.x + a2.x) * ru_ + a3.x;
        au.y = r0.y + (a1.y + a2.y) * ru_ + a3.y;
        au.z = r0.z + (a1.z + a2.z) * ru_ + a3.z;
        au.w = r0.w + (a1.w + a2.w) * ru_ + a3.w;
        oue[d] = r0;
        // pos item acc
        float4 q0 = iemb4[(size_t)pi * DIM4 + d];
        float4 b1 = p14[(size_t)pn * DIM4 + d];
        float4 b2 = p24[(size_t)pn * DIM4 + d];
        float4 b3 = x3c4[(size_t)(BATCH + b) * DIM4 + d];
        float4 ap;
        ap.x = q0.x + (b1.x + b2.x) * rp_ + b3.x;
        ap.y = q0.y + (b1.y + b2.y) * rp_ + b3.y;
        ap.z = q0.z + (b1.z + b2.z) * rp_ + b3.z;
        ap.w = q0.w + (b1.w + b2.w) * rp_ + b3.w;
        ope[d] = q0;
        // neg item acc
        float4 s0 = iemb4[(size_t)ni * DIM4 + d];
        float4 c1 = p14[(size_t)nn * DIM4 + d];
        float4 c2 = p24[(size_t)nn * DIM4 + d];
        float4 c3 = x3c4[(size_t)(2 * BATCH + b) * DIM4 + d];
        float4 an;
        an.x = s0.x + (c1.x + c2.x) * rn_ + c3.x;
        an.y = s0.y + (c1.y + c2.y) * rn_ + c3.y;
        an.z = s0.z + (c1.z + c2.z) * rn_ + c3.z;
        an.w = s0.w + (c1.w + c2.w) * rn_ + c3.w;
        one_[d] = s0;

        ps += au.x * ap.x + au.y * ap.y + au.z * ap.z + au.w * ap.w;
        ns += au.x * an.x + au.y * an.y + au.z * an.z + au.w * an.w;
    }
#pragma unroll
    for (int off = 16; off > 0; off >>= 1) {
        ps += __shfl_down_sync(0xFFFFFFFFu, ps, off);
        ns += __shfl_down_sync(0xFFFFFFFFu, ns, off);
    }
    const float inv16 = 1.0f / 16.0f;   // (1/(N_LAYERS+1))^2
    if (lane == 0) {
        out[b] = ps * inv16;
        out[BATCH + b] = ns * inv16;
    }
}

// ---------------- launch ----------------
extern "C" void kernel_launch(void* const* d_in, const int* in_sizes, int n_in,
                              void* d_out, int out_size) {
    const float* user_emb = (const float*)d_in[0];
    const float* item_emb = (const float*)d_in[1];
    const int* edge_row = (const int*)d_in[2];
    const int* edge_col = (const int*)d_in[3];
    const int* users_idx = (const int*)d_in[4];
    const int* pos_idx = (const int*)d_in[5];
    const int* neg_idx = (const int*)d_in[6];
    float* out = (float*)d_out;

    // graph build
    k_zero_deg<<<(N_NODES + 255) / 256, 256>>>();
    k_count_deg<<<(N_EDGES + 255) / 256, 256>>>(edge_row, edge_col);
    k_scan1<<<SCAN_NB, SCAN_BLK>>>();
    k_scan2<<<1, 512>>>();
    k_scan3<<<(N_NODES + 255) / 256, 256>>>();
    k_scatter<<<(N_EDGES + 255) / 256, 256>>>(edge_row, edge_col);

    // p0 = dinv * x0
    {
        size_t total = (size_t)N_NODES * DIM;
        k_init_p0<<<(int)((total + 255) / 256), 256>>>(user_emb, item_emb);
    }

    // layers 1,2 full; layer 3 only at finalize rows
    int spmm_blocks = (N_NODES + 3) / 4;
    k_spmm_full<<<spmm_blocks, 256>>>(0);   // p0 -> p1
    k_spmm_full<<<spmm_blocks, 256>>>(1);   // p1 -> p2
    k_spmm_sparse<<<(3 * BATCH + 3) / 4, 256>>>(users_idx, pos_idx, neg_idx);

    // outputs
    k_finalize<<<BATCH / 8, 256>>>(users_idx, pos_idx, neg_idx, user_emb, item_emb, out);
}

// round 4
// speedup vs baseline: 3.2502x; 1.8568x over previous
#include <cuda_runtime.h>
#include <cuda_fp16.h>

#define N_USERS 100000
#define N_ITEMS 200000
#define N_NODES (N_USERS + N_ITEMS)
#define DIM 256
#define DIM4 (DIM / 4)
#define DIMH4 (DIM / 8)     // int4 (8 halves) per row = 32
#define N_EDGES 1000000
#define NDIR (2 * N_EDGES)
#define BATCH 8192
#define SCAN_BLK 1024
#define SCAN_NB ((N_NODES + SCAN_BLK - 1) / SCAN_BLK)   // 293

// ---------------- device scratch (static: allowed) ----------------
// propagating buffers store p_l = dinv * x_l  (pre-scaled), fp16
__device__ __half g_p0[(size_t)N_NODES * DIM];   // 154 MB
__device__ __half g_p1[(size_t)N_NODES * DIM];   // 154 MB
__device__ __half g_p2[(size_t)N_NODES * DIM];   // 154 MB
__device__ float  g_x3c[(size_t)3 * BATCH * DIM]; // 25 MB, UNscaled x3 at finalize rows, fp32
__device__ int   g_deg[N_NODES];
__device__ int   g_rowptr[N_NODES + 1];
__device__ int   g_cursor[N_NODES];
__device__ float g_dinv[N_NODES];                // deg^-1/2
__device__ float g_rdeg[N_NODES];                // deg^+1/2 (un-scale factor)
__device__ int   g_csrsrc[NDIR];                 // 8 MB
__device__ int   g_part[SCAN_BLK];

// ---------------- graph preprocessing ----------------
__global__ void k_zero_deg() {
    int i = blockIdx.x * blockDim.x + threadIdx.x;
    if (i < N_NODES) g_deg[i] = 0;
}

__global__ void k_count_deg(const int* __restrict__ erow, const int* __restrict__ ecol) {
    int e = blockIdx.x * blockDim.x + threadIdx.x;
    if (e < N_EDGES) {
        atomicAdd(&g_deg[erow[e]], 1);
        atomicAdd(&g_deg[N_USERS + ecol[e]], 1);
    }
}

__global__ void k_scan1() {
    __shared__ int s[SCAN_BLK];
    int tid = threadIdx.x;
    int i = blockIdx.x * SCAN_BLK + tid;
    int v = (i < N_NODES) ? g_deg[i] : 0;
    s[tid] = v;
    __syncthreads();
    for (int off = 1; off < SCAN_BLK; off <<= 1) {
        int t = (tid >= off) ? s[tid - off] : 0;
        __syncthreads();
        s[tid] += t;
        __syncthreads();
    }
    if (i < N_NODES) g_rowptr[i] = s[tid] - v;
    if (tid == SCAN_BLK - 1) g_part[blockIdx.x] = s[tid];
}

__global__ void k_scan2() {
    __shared__ int s[512];
    int tid = threadIdx.x;
    int v = (tid < SCAN_NB) ? g_part[tid] : 0;
    s[tid] = v;
    __syncthreads();
    for (int off = 1; off < 512; off <<= 1) {
        int t = (tid >= off) ? s[tid - off] : 0;
        __syncthreads();
        s[tid] += t;
        __syncthreads();
    }
    if (tid < SCAN_NB) g_part[tid] = s[tid] - v;
}

__global__ void k_scan3() {
    int i = blockIdx.x * blockDim.x + threadIdx.x;
    if (i < N_NODES) {
        int rp = g_rowptr[i] + g_part[i / SCAN_BLK];
        g_rowptr[i] = rp;
        g_cursor[i] = rp;
        int d = g_deg[i];
        float df = (float)(d < 1 ? 1 : d);
        g_dinv[i] = rsqrtf(df);
        g_rdeg[i] = sqrtf(df);
    }
    if (i == 0) g_rowptr[N_NODES] = NDIR;
}

__global__ void k_scatter(const int* __restrict__ erow, const int* __restrict__ ecol) {
    int e = blockIdx.x * blockDim.x + threadIdx.x;
    if (e < N_EDGES) {
        int u = erow[e];
        int it = N_USERS + ecol[e];
        int p = atomicAdd(&g_cursor[u], 1);
        g_csrsrc[p] = it;
        int q = atomicAdd(&g_cursor[it], 1);
        g_csrsrc[q] = u;
    }
}

// ---------------- init: p0 = half(dinv * concat(user_emb, item_emb)) ----------------
// each thread converts 2 elements (float2 -> half2)
__global__ void k_init_p0(const float* __restrict__ uemb, const float* __restrict__ iemb) {
    size_t i = (size_t)blockIdx.x * blockDim.x + threadIdx.x;   // half2 index
    size_t total = (size_t)N_NODES * DIM / 2;
    if (i >= total) return;
    size_t ei = i * 2;                       // element index
    size_t row = ei >> 8;
    float d = g_dinv[row];
    float2 v;
    if (ei < (size_t)N_USERS * DIM) v = ((const float2*)uemb)[i];
    else v = ((const float2*)iemb)[i - (size_t)N_USERS * DIM / 2];
    ((__half2*)g_p0)[i] = __floats2half2_rn(v.x * d, v.y * d);
}

// ---------------- full propagation: p_out[dst] = half(dinv[dst]^2 * sum_src p_in[src]) --
// warp per dst row; each lane handles 8 halves (one int4); fp32 accumulation.
__global__ void k_spmm_full(int which) {
    const int4* __restrict__ xin = (const int4*)(which == 0 ? g_p0 : g_p1);
    int4* __restrict__ xout = (int4*)(which == 0 ? g_p1 : g_p2);

    int row = blockIdx.x * 8 + (threadIdx.x >> 5);
    int lane = threadIdx.x & 31;
    if (row >= N_NODES) return;

    int beg = g_rowptr[row];
    int end = g_rowptr[row + 1];
    float di = g_dinv[row];
    float w = di * di;

    float a0 = 0.f, a1 = 0.f, a2 = 0.f, a3 = 0.f, a4 = 0.f, a5 = 0.f, a6 = 0.f, a7 = 0.f;
    for (int e = beg; e < end; e++) {
        int s = g_csrsrc[e];
        int4 raw = xin[(size_t)s * DIMH4 + lane];
        float2 f0 = __half22float2(*(__half2*)&raw.x);
        float2 f1 = __half22float2(*(__half2*)&raw.y);
        float2 f2 = __half22float2(*(__half2*)&raw.z);
        float2 f3 = __half22float2(*(__half2*)&raw.w);
        a0 += f0.x; a1 += f0.y; a2 += f1.x; a3 += f1.y;
        a4 += f2.x; a5 += f2.y; a6 += f3.x; a7 += f3.y;
    }
    int4 out;
    __half2 o0 = __floats2half2_rn(a0 * w, a1 * w);
    __half2 o1 = __floats2half2_rn(a2 * w, a3 * w);
    __half2 o2 = __floats2half2_rn(a4 * w, a5 * w);
    __half2 o3 = __floats2half2_rn(a6 * w, a7 * w);
    out.x = *(int*)&o0; out.y = *(int*)&o1; out.z = *(int*)&o2; out.w = *(int*)&o3;
    xout[(size_t)row * DIMH4 + lane] = out;
}

// ---------------- sparse layer 3: only at finalize rows; output UNscaled fp32 x3 --------
__global__ void k_spmm_sparse(const int* __restrict__ uidx, const int* __restrict__ pidx,
                              const int* __restrict__ nidx) {
    int j = blockIdx.x * 8 + (threadIdx.x >> 5);
    int lane = threadIdx.x & 31;
    if (j >= 3 * BATCH) return;

    int node;
    if (j < BATCH) node = uidx[j];
    else if (j < 2 * BATCH) node = N_USERS + pidx[j - BATCH];
    else node = N_USERS + nidx[j - 2 * BATCH];

    int beg = g_rowptr[node];
    int end = g_rowptr[node + 1];
    float di = g_dinv[node];

    const int4* __restrict__ xin = (const int4*)g_p2;
    float a0 = 0.f, a1 = 0.f, a2 = 0.f, a3 = 0.f, a4 = 0.f, a5 = 0.f, a6 = 0.f, a7 = 0.f;
    for (int e = beg; e < end; e++) {
        int s = g_csrsrc[e];
        int4 raw = xin[(size_t)s * DIMH4 + lane];
        float2 f0 = __half22float2(*(__half2*)&raw.x);
        float2 f1 = __half22float2(*(__half2*)&raw.y);
        float2 f2 = __half22float2(*(__half2*)&raw.z);
        float2 f3 = __half22float2(*(__half2*)&raw.w);
        a0 += f0.x; a1 += f0.y; a2 += f1.x; a3 += f1.y;
        a4 += f2.x; a5 += f2.y; a6 += f3.x; a7 += f3.y;
    }
    // x3 = dinv * sum(p2), stored fp32: dims lane*8 .. lane*8+7 -> float4 idx lane*2, lane*2+1
    float4* o = (float4*)g_x3c + (size_t)j * DIM4;
    o[lane * 2]     = make_float4(a0 * di, a1 * di, a2 * di, a3 * di);
    o[lane * 2 + 1] = make_float4(a4 * di, a5 * di, a6 * di, a7 * di);
}

// ---------------- finalize: acc = x0 + (p1+p2)*rdeg + x3 ; dots + raw gathers ----------
// one warp per batch element; lane handles dims [lane*8, lane*8+8)
__device__ __forceinline__ void load8h(const int4* base, size_t row, int lane, float* f) {
    int4 raw = base[row * DIMH4 + lane];
    float2 f0 = __half22float2(*(__half2*)&raw.x);
    float2 f1 = __half22float2(*(__half2*)&raw.y);
    float2 f2 = __half22float2(*(__half2*)&raw.z);
    float2 f3 = __half22float2(*(__half2*)&raw.w);
    f[0] = f0.x; f[1] = f0.y; f[2] = f1.x; f[3] = f1.y;
    f[4] = f2.x; f[5] = f2.y; f[6] = f3.x; f[7] = f3.y;
}

__global__ void k_finalize(const int* __restrict__ uidx, const int* __restrict__ pidx,
                           const int* __restrict__ nidx,
                           const float* __restrict__ uemb, const float* __restrict__ iemb,
                           float* __restrict__ out) {
    int b = blockIdx.x * 8 + (threadIdx.x >> 5);
    int lane = threadIdx.x & 31;
    if (b >= BATCH) return;

    int u = uidx[b];
    int pi = pidx[b];
    int ni = nidx[b];
    int pn = N_USERS + pi;
    int nn = N_USERS + ni;

    float ru_ = g_rdeg[u], rp_ = g_rdeg[pn], rn_ = g_rdeg[nn];

    const int4* p1h = (const int4*)g_p1;
    const int4* p2h = (const int4*)g_p2;
    const float4* uemb4 = (const float4*)uemb;
    const float4* iemb4 = (const float4*)iemb;
    const float4* x3c4 = (const float4*)g_x3c;

    float4* oue = (float4*)(out + 2 * BATCH) + (size_t)b * DIM4;
    float4* ope = (float4*)(out + 2 * BATCH + (size_t)BATCH * DIM) + (size_t)b * DIM4;
    float4* one_ = (float4*)(out + 2 * BATCH + (size_t)2 * BATCH * DIM) + (size_t)b * DIM4;

    float au[8], ap[8], an[8];
    float t1[8], t2[8];

    // ---- user ----
    {
        float4 e0 = uemb4[(size_t)u * DIM4 + lane * 2];
        float4 e1 = uemb4[(size_t)u * DIM4 + lane * 2 + 1];
        float4 x30 = x3c4[(size_t)b * DIM4 + lane * 2];
        float4 x31 = x3c4[(size_t)b * DIM4 + lane * 2 + 1];
        load8h(p1h, (size_t)u, lane, t1);
        load8h(p2h, (size_t)u, lane, t2);
        float e[8] = {e0.x,e0.y,e0.z,e0.w,e1.x,e1.y,e1.z,e1.w};
        float x3[8] = {x30.x,x30.y,x30.z,x30.w,x31.x,x31.y,x31.z,x31.w};
#pragma unroll
        for (int k = 0; k < 8; k++) au[k] = e[k] + (t1[k] + t2[k]) * ru_ + x3[k];
        oue[lane * 2] = e0;
        oue[lane * 2 + 1] = e1;
    }
    // ---- pos item ----
    {
        float4 e0 = iemb4[(size_t)pi * DIM4 + lane * 2];
        float4 e1 = iemb4[(size_t)pi * DIM4 + lane * 2 + 1];
        float4 x30 = x3c4[(size_t)(BATCH + b) * DIM4 + lane * 2];
        float4 x31 = x3c4[(size_t)(BATCH + b) * DIM4 + lane * 2 + 1];
        load8h(p1h, (size_t)pn, lane, t1);
        load8h(p2h, (size_t)pn, lane, t2);
        float e[8] = {e0.x,e0.y,e0.z,e0.w,e1.x,e1.y,e1.z,e1.w};
        float x3[8] = {x30.x,x30.y,x30.z,x30.w,x31.x,x31.y,x31.z,x31.w};
#pragma unroll
        for (int k = 0; k < 8; k++) ap[k] = e[k] + (t1[k] + t2[k]) * rp_ + x3[k];
        ope[lane * 2] = e0;
        ope[lane * 2 + 1] = e1;
    }
    // ---- neg item ----
    {
        float4 e0 = iemb4[(size_t)ni * DIM4 + lane * 2];
        float4 e1 = iemb4[(size_t)ni * DIM4 + lane * 2 + 1];
        float4 x30 = x3c4[(size_t)(2 * BATCH + b) * DIM4 + lane * 2];
        float4 x31 = x3c4[(size_t)(2 * BATCH + b) * DIM4 + lane * 2 + 1];
        load8h(p1h, (size_t)nn, lane, t1);
        load8h(p2h, (size_t)nn, lane, t2);
        float e[8] = {e0.x,e0.y,e0.z,e0.w,e1.x,e1.y,e1.z,e1.w};
        float x3[8] = {x30.x,x30.y,x30.z,x30.w,x31.x,x31.y,x31.z,x31.w};
#pragma unroll
        for (int k = 0; k < 8; k++) an[k] = e[k] + (t1[k] + t2[k]) * rn_ + x3[k];
        one_[lane * 2] = e0;
        one_[lane * 2 + 1] = e1;
    }

    float ps = 0.f, ns = 0.f;
#pragma unroll
    for (int k = 0; k < 8; k++) {
        ps += au[k] * ap[k];
        ns += au[k] * an[k];
    }
#pragma unroll
    for (int off = 16; off > 0; off >>= 1) {
        ps += __shfl_down_sync(0xFFFFFFFFu, ps, off);
        ns += __shfl_down_sync(0xFFFFFFFFu, ns, off);
    }
    const float inv16 = 1.0f / 16.0f;   // (1/(N_LAYERS+1))^2
    if (lane == 0) {
        out[b] = ps * inv16;
        out[BATCH + b] = ns * inv16;
    }
}

// ---------------- launch ----------------
extern "C" void kernel_launch(void* const* d_in, const int* in_sizes, int n_in,
                              void* d_out, int out_size) {
    const float* user_emb = (const float*)d_in[0];
    const float* item_emb = (const float*)d_in[1];
    const int* edge_row = (const int*)d_in[2];
    const int* edge_col = (const int*)d_in[3];
    const int* users_idx = (const int*)d_in[4];
    const int* pos_idx = (const int*)d_in[5];
    const int* neg_idx = (const int*)d_in[6];
    float* out = (float*)d_out;

    // graph build
    k_zero_deg<<<(N_NODES + 255) / 256, 256>>>();
    k_count_deg<<<(N_EDGES + 255) / 256, 256>>>(edge_row, edge_col);
    k_scan1<<<SCAN_NB, SCAN_BLK>>>();
    k_scan2<<<1, 512>>>();
    k_scan3<<<(N_NODES + 255) / 256, 256>>>();
    k_scatter<<<(N_EDGES + 255) / 256, 256>>>(edge_row, edge_col);

    // p0 = half(dinv * x0)
    {
        size_t total = (size_t)N_NODES * DIM / 2;
        k_init_p0<<<(int)((total + 255) / 256), 256>>>(user_emb, item_emb);
    }

    // layers 1,2 full; layer 3 only at finalize rows
    int spmm_blocks = (N_NODES + 7) / 8;
    k_spmm_full<<<spmm_blocks, 256>>>(0);   // p0 -> p1
    k_spmm_full<<<spmm_blocks, 256>>>(1);   // p1 -> p2
    k_spmm_sparse<<<(3 * BATCH + 7) / 8, 256>>>(users_idx, pos_idx, neg_idx);

    // outputs
    k_finalize<<<BATCH / 8, 256>>>(users_idx, pos_idx, neg_idx, user_emb, item_emb, out);
}

// round 5
// speedup vs baseline: 3.4849x; 1.0722x over previous
#include <cuda_runtime.h>
#include <cuda_fp16.h>

#define N_USERS 100000
#define N_ITEMS 200000
#define N_NODES (N_USERS + N_ITEMS)
#define DIM 256
#define DIM4 (DIM / 4)
#define DIMH4 (DIM / 8)     // int4 (8 halves) per row = 32
#define N_EDGES 1000000
#define NDIR (2 * N_EDGES)
#define BATCH 8192
#define SCAN_BLK 1024
#define SCAN_NB ((N_NODES + SCAN_BLK - 1) / SCAN_BLK)   // 293

// ---------------- device scratch (static: allowed) ----------------
// propagating buffers store p_l = dinv * x_l  (pre-scaled), fp16
__device__ __half g_p0[(size_t)N_NODES * DIM];   // 154 MB
__device__ __half g_p1[(size_t)N_NODES * DIM];   // 154 MB
__device__ __half g_p2[(size_t)N_NODES * DIM];   // 154 MB
__device__ int   g_deg[N_NODES];
__device__ int   g_rowptr[N_NODES + 1];
__device__ int   g_cursor[N_NODES];
__device__ float g_dinv[N_NODES];                // deg^-1/2
__device__ float g_rdeg[N_NODES];                // deg^+1/2 (un-scale factor)
__device__ int   g_csrsrc[NDIR];                 // 8 MB
__device__ int   g_part[SCAN_BLK];
__device__ unsigned char g_need2[N_NODES];       // rows where p2 must be valid

// ---------------- graph preprocessing ----------------
__global__ void k_zero_deg() {
    int i = blockIdx.x * blockDim.x + threadIdx.x;
    if (i < N_NODES) { g_deg[i] = 0; g_need2[i] = 0; }
}

__global__ void k_count_deg(const int* __restrict__ erow, const int* __restrict__ ecol) {
    int e = blockIdx.x * blockDim.x + threadIdx.x;
    if (e < N_EDGES) {
        atomicAdd(&g_deg[erow[e]], 1);
        atomicAdd(&g_deg[N_USERS + ecol[e]], 1);
    }
}

__global__ void k_scan1() {
    __shared__ int s[SCAN_BLK];
    int tid = threadIdx.x;
    int i = blockIdx.x * SCAN_BLK + tid;
    int v = (i < N_NODES) ? g_deg[i] : 0;
    s[tid] = v;
    __syncthreads();
    for (int off = 1; off < SCAN_BLK; off <<= 1) {
        int t = (tid >= off) ? s[tid - off] : 0;
        __syncthreads();
        s[tid] += t;
        __syncthreads();
    }
    if (i < N_NODES) g_rowptr[i] = s[tid] - v;
    if (tid == SCAN_BLK - 1) g_part[blockIdx.x] = s[tid];
}

__global__ void k_scan2() {
    __shared__ int s[512];
    int tid = threadIdx.x;
    int v = (tid < SCAN_NB) ? g_part[tid] : 0;
    s[tid] = v;
    __syncthreads();
    for (int off = 1; off < 512; off <<= 1) {
        int t = (tid >= off) ? s[tid - off] : 0;
        __syncthreads();
        s[tid] += t;
        __syncthreads();
    }
    if (tid < SCAN_NB) g_part[tid] = s[tid] - v;
}

__global__ void k_scan3() {
    int i = blockIdx.x * blockDim.x + threadIdx.x;
    if (i < N_NODES) {
        int rp = g_rowptr[i] + g_part[i / SCAN_BLK];
        g_rowptr[i] = rp;
        g_cursor[i] = rp;
        int d = g_deg[i];
        float df = (float)(d < 1 ? 1 : d);
        g_dinv[i] = rsqrtf(df);
        g_rdeg[i] = sqrtf(df);
    }
    if (i == 0) g_rowptr[N_NODES] = NDIR;
}

__global__ void k_scatter(const int* __restrict__ erow, const int* __restrict__ ecol) {
    int e = blockIdx.x * blockDim.x + threadIdx.x;
    if (e < N_EDGES) {
        int u = erow[e];
        int it = N_USERS + ecol[e];
        int p = atomicAdd(&g_cursor[u], 1);
        g_csrsrc[p] = it;
        int q = atomicAdd(&g_cursor[it], 1);
        g_csrsrc[q] = u;
    }
}

// ---------------- mark rows whose p2 is needed: batch nodes + their neighbors ----------
// warp per batch slot; lanes stride the adjacency list. Idempotent byte stores.
__global__ void k_mark(const int* __restrict__ uidx, const int* __restrict__ pidx,
                       const int* __restrict__ nidx) {
    int j = blockIdx.x * 8 + (threadIdx.x >> 5);
    int lane = threadIdx.x & 31;
    if (j >= 3 * BATCH) return;
    int node;
    if (j < BATCH) node = uidx[j];
    else if (j < 2 * BATCH) node = N_USERS + pidx[j - BATCH];
    else node = N_USERS + nidx[j - 2 * BATCH];
    if (lane == 0) g_need2[node] = 1;
    int beg = g_rowptr[node];
    int end = g_rowptr[node + 1];
    for (int e = beg + lane; e < end; e += 32) {
        g_need2[g_csrsrc[e]] = 1;
    }
}

// ---------------- init: p0 = half(dinv * concat(user_emb, item_emb)) ----------------
__global__ void k_init_p0(const float* __restrict__ uemb, const float* __restrict__ iemb) {
    size_t i = (size_t)blockIdx.x * blockDim.x + threadIdx.x;   // half2 index
    size_t total = (size_t)N_NODES * DIM / 2;
    if (i >= total) return;
    size_t ei = i * 2;                       // element index
    size_t row = ei >> 8;
    float d = g_dinv[row];
    float2 v;
    if (ei < (size_t)N_USERS * DIM) v = ((const float2*)uemb)[i];
    else v = ((const float2*)iemb)[i - (size_t)N_USERS * DIM / 2];
    ((__half2*)g_p0)[i] = __floats2half2_rn(v.x * d, v.y * d);
}

// ---------------- full propagation: p_out[dst] = half(dinv[dst]^2 * sum_src p_in[src]) --
// warp per dst row; lane handles 8 halves (one int4); fp32 accumulation.
// use_flag: skip rows where g_need2==0 (layer 2 only).
__global__ void k_spmm_full(int which, int use_flag) {
    const int4* __restrict__ xin = (const int4*)(which == 0 ? g_p0 : g_p1);
    int4* __restrict__ xout = (int4*)(which == 0 ? g_p1 : g_p2);

    int row = blockIdx.x * 8 + (threadIdx.x >> 5);
    int lane = threadIdx.x & 31;
    if (row >= N_NODES) return;
    if (use_flag && !g_need2[row]) return;

    int beg = g_rowptr[row];
    int end = g_rowptr[row + 1];
    float di = g_dinv[row];
    float w = di * di;

    float a0 = 0.f, a1 = 0.f, a2 = 0.f, a3 = 0.f, a4 = 0.f, a5 = 0.f, a6 = 0.f, a7 = 0.f;
    for (int e = beg; e < end; e++) {
        int s = g_csrsrc[e];
        int4 raw = xin[(size_t)s * DIMH4 + lane];
        float2 f0 = __half22float2(*(__half2*)&raw.x);
        float2 f1 = __half22float2(*(__half2*)&raw.y);
        float2 f2 = __half22float2(*(__half2*)&raw.z);
        float2 f3 = __half22float2(*(__half2*)&raw.w);
        a0 += f0.x; a1 += f0.y; a2 += f1.x; a3 += f1.y;
        a4 += f2.x; a5 += f2.y; a6 += f3.x; a7 += f3.y;
    }
    int4 out;
    __half2 o0 = __floats2half2_rn(a0 * w, a1 * w);
    __half2 o1 = __floats2half2_rn(a2 * w, a3 * w);
    __half2 o2 = __floats2half2_rn(a4 * w, a5 * w);
    __half2 o3 = __floats2half2_rn(a6 * w, a7 * w);
    out.x = *(int*)&o0; out.y = *(int*)&o1; out.z = *(int*)&o2; out.w = *(int*)&o3;
    xout[(size_t)row * DIMH4 + lane] = out;
}

// ---------------- fused finalize: per node, x3 = dinv*sum_nbr(p2); acc = x0+(p1+p2)*rdeg+x3
// one warp per batch element; lane handles dims [lane*8, lane*8+8)
__device__ __forceinline__ void load8h(const int4* base, size_t row, int lane, float* f) {
    int4 raw = base[row * DIMH4 + lane];
    float2 f0 = __half22float2(*(__half2*)&raw.x);
    float2 f1 = __half22float2(*(__half2*)&raw.y);
    float2 f2 = __half22float2(*(__half2*)&raw.z);
    float2 f3 = __half22float2(*(__half2*)&raw.w);
    f[0] = f0.x; f[1] = f0.y; f[2] = f1.x; f[3] = f1.y;
    f[4] = f2.x; f[5] = f2.y; f[6] = f3.x; f[7] = f3.y;
}

// compute acc[0..8) for node; also writes raw embedding row to rawout
__device__ __forceinline__ void node_acc(int node, const float4* __restrict__ emb4,
                                         size_t embrow, int lane,
                                         float* acc, float4* __restrict__ rawout) {
    const int4* p1h = (const int4*)g_p1;
    const int4* p2h = (const int4*)g_p2;

    int beg = g_rowptr[node];
    int end = g_rowptr[node + 1];
    float di = g_dinv[node];
    float rd = g_rdeg[node];

    // x3 gather over neighbors' p2
    float a0 = 0.f, a1 = 0.f, a2 = 0.f, a3 = 0.f, a4 = 0.f, a5 = 0.f, a6 = 0.f, a7 = 0.f;
    for (int e = beg; e < end; e++) {
        int s = g_csrsrc[e];
        int4 raw = p2h[(size_t)s * DIMH4 + lane];
        float2 f0 = __half22float2(*(__half2*)&raw.x);
        float2 f1 = __half22float2(*(__half2*)&raw.y);
        float2 f2 = __half22float2(*(__half2*)&raw.z);
        float2 f3 = __half22float2(*(__half2*)&raw.w);
        a0 += f0.x; a1 += f0.y; a2 += f1.x; a3 += f1.y;
        a4 += f2.x; a5 += f2.y; a6 += f3.x; a7 += f3.y;
    }
    float x3[8] = {a0 * di, a1 * di, a2 * di, a3 * di, a4 * di, a5 * di, a6 * di, a7 * di};

    float4 e0 = emb4[embrow * DIM4 + lane * 2];
    float4 e1 = emb4[embrow * DIM4 + lane * 2 + 1];
    float e[8] = {e0.x, e0.y, e0.z, e0.w, e1.x, e1.y, e1.z, e1.w};

    float t1[8], t2[8];
    load8h(p1h, (size_t)node, lane, t1);
    load8h(p2h, (size_t)node, lane, t2);
#pragma unroll
    for (int k = 0; k < 8; k++) acc[k] = e[k] + (t1[k] + t2[k]) * rd + x3[k];

    rawout[lane * 2] = e0;
    rawout[lane * 2 + 1] = e1;
}

__global__ void k_finalize(const int* __restrict__ uidx, const int* __restrict__ pidx,
                           const int* __restrict__ nidx,
                           const float* __restrict__ uemb, const float* __restrict__ iemb,
                           float* __restrict__ out) {
    int b = blockIdx.x * 8 + (threadIdx.x >> 5);
    int lane = threadIdx.x & 31;
    if (b >= BATCH) return;

    int u = uidx[b];
    int pi = pidx[b];
    int ni = nidx[b];

    float4* oue = (float4*)(out + 2 * BATCH) + (size_t)b * DIM4;
    float4* ope = (float4*)(out + 2 * BATCH + (size_t)BATCH * DIM) + (size_t)b * DIM4;
    float4* one_ = (float4*)(out + 2 * BATCH + (size_t)2 * BATCH * DIM) + (size_t)b * DIM4;

    float au[8], ap[8], an[8];
    node_acc(u, (const float4*)uemb, (size_t)u, lane, au, oue);
    node_acc(N_USERS + pi, (const float4*)iemb, (size_t)pi, lane, ap, ope);
    node_acc(N_USERS + ni, (const float4*)iemb, (size_t)ni, lane, an, one_);

    float ps = 0.f, ns = 0.f;
#pragma unroll
    for (int k = 0; k < 8; k++) {
        ps += au[k] * ap[k];
        ns += au[k] * an[k];
    }
#pragma unroll
    for (int off = 16; off > 0; off >>= 1) {
        ps += __shfl_down_sync(0xFFFFFFFFu, ps, off);
        ns += __shfl_down_sync(0xFFFFFFFFu, ns, off);
    }
    const float inv16 = 1.0f / 16.0f;   // (1/(N_LAYERS+1))^2
    if (lane == 0) {
        out[b] = ps * inv16;
        out[BATCH + b] = ns * inv16;
    }
}

// ---------------- launch ----------------
extern "C" void kernel_launch(void* const* d_in, const int* in_sizes, int n_in,
                              void* d_out, int out_size) {
    const float* user_emb = (const float*)d_in[0];
    const float* item_emb = (const float*)d_in[1];
    const int* edge_row = (const int*)d_in[2];
    const int* edge_col = (const int*)d_in[3];
    const int* users_idx = (const int*)d_in[4];
    const int* pos_idx = (const int*)d_in[5];
    const int* neg_idx = (const int*)d_in[6];
    float* out = (float*)d_out;

    // graph build
    k_zero_deg<<<(N_NODES + 255) / 256, 256>>>();
    k_count_deg<<<(N_EDGES + 255) / 256, 256>>>(edge_row, edge_col);
    k_scan1<<<SCAN_NB, SCAN_BLK>>>();
    k_scan2<<<1, 512>>>();
    k_scan3<<<(N_NODES + 255) / 256, 256>>>();
    k_scatter<<<(N_EDGES + 255) / 256, 256>>>(edge_row, edge_col);

    // mark rows needed in layer 2 (batch nodes + 1-hop neighbors)
    k_mark<<<(3 * BATCH + 7) / 8, 256>>>(users_idx, pos_idx, neg_idx);

    // p0 = half(dinv * x0)
    {
        size_t total = (size_t)N_NODES * DIM / 2;
        k_init_p0<<<(int)((total + 255) / 256), 256>>>(user_emb, item_emb);
    }

    // layer 1 full; layer 2 only at marked rows
    int spmm_blocks = (N_NODES + 7) / 8;
    k_spmm_full<<<spmm_blocks, 256>>>(0, 0);   // p0 -> p1 (all rows)
    k_spmm_full<<<spmm_blocks, 256>>>(1, 1);   // p1 -> p2 (marked rows only)

    // fused sparse layer 3 + outputs
    k_finalize<<<BATCH / 8, 256>>>(users_idx, pos_idx, neg_idx, user_emb, item_emb, out);
}

// round 6
// speedup vs baseline: 3.5489x; 1.0184x over previous
#include <cuda_runtime.h>
#include <cuda_fp16.h>

#define N_USERS 100000
#define N_ITEMS 200000
#define N_NODES (N_USERS + N_ITEMS)
#define DIM 256
#define DIM4 (DIM / 4)
#define DIMH4 (DIM / 8)     // int4 (8 halves) per row = 32
#define N_EDGES 1000000
#define NDIR (2 * N_EDGES)
#define BATCH 8192
#define SCAN_BLK 1024
#define SCAN_NB ((N_NODES + SCAN_BLK - 1) / SCAN_BLK)   // 293

// ---------------- device scratch (static: allowed) ----------------
// propagating buffers store p_l = dinv * x_l  (pre-scaled), fp16
__device__ __half g_p0[(size_t)N_NODES * DIM];   // 154 MB
__device__ __half g_p1[(size_t)N_NODES * DIM];   // 154 MB
__device__ __half g_p2[(size_t)N_NODES * DIM];   // 154 MB
__device__ int   g_deg[N_NODES];
__device__ int   g_rowptr[N_NODES + 1];
__device__ int   g_cursor[N_NODES];
__device__ float g_dinv[N_NODES];                // deg^-1/2
__device__ float g_rdeg[N_NODES];                // deg^+1/2 (un-scale factor)
__device__ int   g_csrsrc[NDIR];                 // 8 MB
__device__ int   g_part[SCAN_BLK];
__device__ unsigned char g_need2[N_NODES];       // rows where p2 must be valid

// ---------------- accumulator helpers ----------------
struct Acc8 {
    float a0, a1, a2, a3, a4, a5, a6, a7;
    __device__ __forceinline__ void init() {
        a0 = a1 = a2 = a3 = a4 = a5 = a6 = a7 = 0.f;
    }
    __device__ __forceinline__ void add(const int4& raw) {
        float2 f0 = __half22float2(*(__half2*)&raw.x);
        float2 f1 = __half22float2(*(__half2*)&raw.y);
        float2 f2 = __half22float2(*(__half2*)&raw.z);
        float2 f3 = __half22float2(*(__half2*)&raw.w);
        a0 += f0.x; a1 += f0.y; a2 += f1.x; a3 += f1.y;
        a4 += f2.x; a5 += f2.y; a6 += f3.x; a7 += f3.y;
    }
};

// gather-sum over adjacency [beg,end) from fp16 buffer, 4x unrolled for MLP
__device__ __forceinline__ void gather_sum(const int4* __restrict__ xin, int beg, int end,
                                           int lane, Acc8& acc) {
    int e = beg;
    for (; e + 4 <= end; e += 4) {
        int s0 = g_csrsrc[e];
        int s1 = g_csrsrc[e + 1];
        int s2 = g_csrsrc[e + 2];
        int s3 = g_csrsrc[e + 3];
        int4 r0 = xin[(size_t)s0 * DIMH4 + lane];
        int4 r1 = xin[(size_t)s1 * DIMH4 + lane];
        int4 r2 = xin[(size_t)s2 * DIMH4 + lane];
        int4 r3 = xin[(size_t)s3 * DIMH4 + lane];
        acc.add(r0);
        acc.add(r1);
        acc.add(r2);
        acc.add(r3);
    }
    for (; e < end; e++) {
        int s = g_csrsrc[e];
        int4 r = xin[(size_t)s * DIMH4 + lane];
        acc.add(r);
    }
}

// ---------------- graph preprocessing ----------------
__global__ void k_zero_deg() {
    int i = blockIdx.x * blockDim.x + threadIdx.x;
    if (i < N_NODES) { g_deg[i] = 0; g_need2[i] = 0; }
}

__global__ void k_count_deg(const int* __restrict__ erow, const int* __restrict__ ecol) {
    int e = blockIdx.x * blockDim.x + threadIdx.x;
    if (e < N_EDGES) {
        atomicAdd(&g_deg[erow[e]], 1);
        atomicAdd(&g_deg[N_USERS + ecol[e]], 1);
    }
}

__global__ void k_scan1() {
    __shared__ int s[SCAN_BLK];
    int tid = threadIdx.x;
    int i = blockIdx.x * SCAN_BLK + tid;
    int v = (i < N_NODES) ? g_deg[i] : 0;
    s[tid] = v;
    __syncthreads();
    for (int off = 1; off < SCAN_BLK; off <<= 1) {
        int t = (tid >= off) ? s[tid - off] : 0;
        __syncthreads();
        s[tid] += t;
        __syncthreads();
    }
    if (i < N_NODES) g_rowptr[i] = s[tid] - v;
    if (tid == SCAN_BLK - 1) g_part[blockIdx.x] = s[tid];
}

__global__ void k_scan2() {
    __shared__ int s[512];
    int tid = threadIdx.x;
    int v = (tid < SCAN_NB) ? g_part[tid] : 0;
    s[tid] = v;
    __syncthreads();
    for (int off = 1; off < 512; off <<= 1) {
        int t = (tid >= off) ? s[tid - off] : 0;
        __syncthreads();
        s[tid] += t;
        __syncthreads();
    }
    if (tid < SCAN_NB) g_part[tid] = s[tid] - v;
}

__global__ void k_scan3() {
    int i = blockIdx.x * blockDim.x + threadIdx.x;
    if (i < N_NODES) {
        int rp = g_rowptr[i] + g_part[i / SCAN_BLK];
        g_rowptr[i] = rp;
        g_cursor[i] = rp;
        int d = g_deg[i];
        float df = (float)(d < 1 ? 1 : d);
        g_dinv[i] = rsqrtf(df);
        g_rdeg[i] = sqrtf(df);
    }
    if (i == 0) g_rowptr[N_NODES] = NDIR;
}

__global__ void k_scatter(const int* __restrict__ erow, const int* __restrict__ ecol) {
    int e = blockIdx.x * blockDim.x + threadIdx.x;
    if (e < N_EDGES) {
        int u = erow[e];
        int it = N_USERS + ecol[e];
        int p = atomicAdd(&g_cursor[u], 1);
        g_csrsrc[p] = it;
        int q = atomicAdd(&g_cursor[it], 1);
        g_csrsrc[q] = u;
    }
}

// ---------------- mark rows whose p2 is needed: batch nodes + their neighbors ----------
__global__ void k_mark(const int* __restrict__ uidx, const int* __restrict__ pidx,
                       const int* __restrict__ nidx) {
    int j = blockIdx.x * 8 + (threadIdx.x >> 5);
    int lane = threadIdx.x & 31;
    if (j >= 3 * BATCH) return;
    int node;
    if (j < BATCH) node = uidx[j];
    else if (j < 2 * BATCH) node = N_USERS + pidx[j - BATCH];
    else node = N_USERS + nidx[j - 2 * BATCH];
    if (lane == 0) g_need2[node] = 1;
    int beg = g_rowptr[node];
    int end = g_rowptr[node + 1];
    for (int e = beg + lane; e < end; e += 32) {
        g_need2[g_csrsrc[e]] = 1;
    }
}

// ---------------- init: p0 = half(dinv * concat(user_emb, item_emb)) ----------------
__global__ void k_init_p0(const float* __restrict__ uemb, const float* __restrict__ iemb) {
    size_t i = (size_t)blockIdx.x * blockDim.x + threadIdx.x;   // half2 index
    size_t total = (size_t)N_NODES * DIM / 2;
    if (i >= total) return;
    size_t ei = i * 2;                       // element index
    size_t row = ei >> 8;
    float d = g_dinv[row];
    float2 v;
    if (ei < (size_t)N_USERS * DIM) v = ((const float2*)uemb)[i];
    else v = ((const float2*)iemb)[i - (size_t)N_USERS * DIM / 2];
    ((__half2*)g_p0)[i] = __floats2half2_rn(v.x * d, v.y * d);
}

// ---------------- full propagation: p_out[dst] = half(dinv[dst]^2 * sum_src p_in[src]) --
// warp per dst row; lane handles 8 halves (one int4); fp32 accumulation; 4x-unrolled MLP.
__global__ void __launch_bounds__(256) k_spmm_full(int which, int use_flag) {
    const int4* __restrict__ xin = (const int4*)(which == 0 ? g_p0 : g_p1);
    int4* __restrict__ xout = (int4*)(which == 0 ? g_p1 : g_p2);

    int row = blockIdx.x * 8 + (threadIdx.x >> 5);
    int lane = threadIdx.x & 31;
    if (row >= N_NODES) return;
    if (use_flag && !g_need2[row]) return;

    int beg = g_rowptr[row];
    int end = g_rowptr[row + 1];
    float di = g_dinv[row];
    float w = di * di;

    Acc8 acc;
    acc.init();
    gather_sum(xin, beg, end, lane, acc);

    int4 out;
    __half2 o0 = __floats2half2_rn(acc.a0 * w, acc.a1 * w);
    __half2 o1 = __floats2half2_rn(acc.a2 * w, acc.a3 * w);
    __half2 o2 = __floats2half2_rn(acc.a4 * w, acc.a5 * w);
    __half2 o3 = __floats2half2_rn(acc.a6 * w, acc.a7 * w);
    out.x = *(int*)&o0; out.y = *(int*)&o1; out.z = *(int*)&o2; out.w = *(int*)&o3;
    xout[(size_t)row * DIMH4 + lane] = out;
}

// ---------------- fused finalize ----------------
__device__ __forceinline__ void load8h(const int4* base, size_t row, int lane, float* f) {
    int4 raw = base[row * DIMH4 + lane];
    float2 f0 = __half22float2(*(__half2*)&raw.x);
    float2 f1 = __half22float2(*(__half2*)&raw.y);
    float2 f2 = __half22float2(*(__half2*)&raw.z);
    float2 f3 = __half22float2(*(__half2*)&raw.w);
    f[0] = f0.x; f[1] = f0.y; f[2] = f1.x; f[3] = f1.y;
    f[4] = f2.x; f[5] = f2.y; f[6] = f3.x; f[7] = f3.y;
}

// compute acc[0..8) for node; also writes raw embedding row to rawout
__device__ __forceinline__ void node_acc(int node, const float4* __restrict__ emb4,
                                         size_t embrow, int lane,
                                         float* accv, float4* __restrict__ rawout) {
    const int4* p1h = (const int4*)g_p1;
    const int4* p2h = (const int4*)g_p2;

    int beg = g_rowptr[node];
    int end = g_rowptr[node + 1];
    float di = g_dinv[node];
    float rd = g_rdeg[node];

    // x3 gather over neighbors' p2 (4x-unrolled)
    Acc8 acc;
    acc.init();
    gather_sum(p2h, beg, end, lane, acc);
    float x3[8] = {acc.a0 * di, acc.a1 * di, acc.a2 * di, acc.a3 * di,
                   acc.a4 * di, acc.a5 * di, acc.a6 * di, acc.a7 * di};

    float4 e0 = emb4[embrow * DIM4 + lane * 2];
    float4 e1 = emb4[embrow * DIM4 + lane * 2 + 1];
    float e[8] = {e0.x, e0.y, e0.z, e0.w, e1.x, e1.y, e1.z, e1.w};

    float t1[8], t2[8];
    load8h(p1h, (size_t)node, lane, t1);
    load8h(p2h, (size_t)node, lane, t2);
#pragma unroll
    for (int k = 0; k < 8; k++) accv[k] = e[k] + (t1[k] + t2[k]) * rd + x3[k];

    rawout[lane * 2] = e0;
    rawout[lane * 2 + 1] = e1;
}

__global__ void __launch_bounds__(256) k_finalize(
        const int* __restrict__ uidx, const int* __restrict__ pidx,
        const int* __restrict__ nidx,
        const float* __restrict__ uemb, const float* __restrict__ iemb,
        float* __restrict__ out) {
    int b = blockIdx.x * 8 + (threadIdx.x >> 5);
    int lane = threadIdx.x & 31;
    if (b >= BATCH) return;

    int u = uidx[b];
    int pi = pidx[b];
    int ni = nidx[b];

    float4* oue = (float4*)(out + 2 * BATCH) + (size_t)b * DIM4;
    float4* ope = (float4*)(out + 2 * BATCH + (size_t)BATCH * DIM) + (size_t)b * DIM4;
    float4* one_ = (float4*)(out + 2 * BATCH + (size_t)2 * BATCH * DIM) + (size_t)b * DIM4;

    float au[8], ap[8], an[8];
    node_acc(u, (const float4*)uemb, (size_t)u, lane, au, oue);
    node_acc(N_USERS + pi, (const float4*)iemb, (size_t)pi, lane, ap, ope);
    node_acc(N_USERS + ni, (const float4*)iemb, (size_t)ni, lane, an, one_);

    float ps = 0.f, ns = 0.f;
#pragma unroll
    for (int k = 0; k < 8; k++) {
        ps += au[k] * ap[k];
        ns += au[k] * an[k];
    }
#pragma unroll
    for (int off = 16; off > 0; off >>= 1) {
        ps += __shfl_down_sync(0xFFFFFFFFu, ps, off);
        ns += __shfl_down_sync(0xFFFFFFFFu, ns, off);
    }
    const float inv16 = 1.0f / 16.0f;   // (1/(N_LAYERS+1))^2
    if (lane == 0) {
        out[b] = ps * inv16;
        out[BATCH + b] = ns * inv16;
    }
}

// ---------------- launch ----------------
extern "C" void kernel_launch(void* const* d_in, const int* in_sizes, int n_in,
                              void* d_out, int out_size) {
    const float* user_emb = (const float*)d_in[0];
    const float* item_emb = (const float*)d_in[1];
    const int* edge_row = (const int*)d_in[2];
    const int* edge_col = (const int*)d_in[3];
    const int* users_idx = (const int*)d_in[4];
    const int* pos_idx = (const int*)d_in[5];
    const int* neg_idx = (const int*)d_in[6];
    float* out = (float*)d_out;

    // graph build
    k_zero_deg<<<(N_NODES + 255) / 256, 256>>>();
    k_count_deg<<<(N_EDGES + 255) / 256, 256>>>(edge_row, edge_col);
    k_scan1<<<SCAN_NB, SCAN_BLK>>>();
    k_scan2<<<1, 512>>>();
    k_scan3<<<(N_NODES + 255) / 256, 256>>>();
    k_scatter<<<(N_EDGES + 255) / 256, 256>>>(edge_row, edge_col);

    // mark rows needed in layer 2 (batch nodes + 1-hop neighbors)
    k_mark<<<(3 * BATCH + 7) / 8, 256>>>(users_idx, pos_idx, neg_idx);

    // p0 = half(dinv * x0)
    {
        size_t total = (size_t)N_NODES * DIM / 2;
        k_init_p0<<<(int)((total + 255) / 256), 256>>>(user_emb, item_emb);
    }

    // layer 1 full; layer 2 only at marked rows
    int spmm_blocks = (N_NODES + 7) / 8;
    k_spmm_full<<<spmm_blocks, 256>>>(0, 0);   // p0 -> p1 (all rows)
    k_spmm_full<<<spmm_blocks, 256>>>(1, 1);   // p1 -> p2 (marked rows only)

    // fused sparse layer 3 + outputs
    k_finalize<<<BATCH / 8, 256>>>(users_idx, pos_idx, neg_idx, user_emb, item_emb, out);
}

// round 7
// speedup vs baseline: 3.5684x; 1.0055x over previous
#include <cuda_runtime.h>
#include <cuda_fp16.h>

#define N_USERS 100000
#define N_ITEMS 200000
#define N_NODES (N_USERS + N_ITEMS)
#define DIM 256
#define DIM4 (DIM / 4)
#define DIMH4 (DIM / 8)     // int4 (8 halves) per row = 32
#define N_EDGES 1000000
#define NDIR (2 * N_EDGES)
#define BATCH 8192
#define SCAN_BLK 1024
#define SCAN_NB ((N_NODES + SCAN_BLK - 1) / SCAN_BLK)   // 293
#define SCATTER_BLOCKS ((N_EDGES + 255) / 256)          // 3907
#define INIT_H2 ((size_t)N_NODES * DIM / 2)             // 38.4M half2
#define INIT_BLOCKS ((int)((INIT_H2 + 255) / 256))

// ---------------- device scratch (static: allowed) ----------------
// propagating buffers store p_l = dinv * x_l  (pre-scaled), fp16
__device__ __half g_p0[(size_t)N_NODES * DIM];   // 154 MB
__device__ __half g_p1[(size_t)N_NODES * DIM];   // 154 MB
__device__ __half g_p2[(size_t)N_NODES * DIM];   // 154 MB
__device__ int   g_deg[N_NODES];
__device__ int   g_rowptr[N_NODES + 1];
__device__ int   g_cursor[N_NODES];
__device__ float g_dinv[N_NODES];                // deg^-1/2
__device__ float g_rdeg[N_NODES];                // deg^+1/2 (un-scale factor)
__device__ int   g_csrsrc[NDIR];                 // 8 MB
__device__ int   g_part[SCAN_BLK];
__device__ unsigned char g_need2[N_NODES];       // rows where p2 must be valid

// ---------------- accumulator helpers ----------------
struct Acc8 {
    float a0, a1, a2, a3, a4, a5, a6, a7;
    __device__ __forceinline__ void init() {
        a0 = a1 = a2 = a3 = a4 = a5 = a6 = a7 = 0.f;
    }
    __device__ __forceinline__ void add(const int4& raw) {
        float2 f0 = __half22float2(*(__half2*)&raw.x);
        float2 f1 = __half22float2(*(__half2*)&raw.y);
        float2 f2 = __half22float2(*(__half2*)&raw.z);
        float2 f3 = __half22float2(*(__half2*)&raw.w);
        a0 += f0.x; a1 += f0.y; a2 += f1.x; a3 += f1.y;
        a4 += f2.x; a5 += f2.y; a6 += f3.x; a7 += f3.y;
    }
};

// gather-sum over adjacency [beg,end) from fp16 buffer, 4x unrolled for MLP
__device__ __forceinline__ void gather_sum(const int4* __restrict__ xin, int beg, int end,
                                           int lane, Acc8& acc) {
    int e = beg;
    for (; e + 4 <= end; e += 4) {
        int s0 = g_csrsrc[e];
        int s1 = g_csrsrc[e + 1];
        int s2 = g_csrsrc[e + 2];
        int s3 = g_csrsrc[e + 3];
        int4 r0 = xin[(size_t)s0 * DIMH4 + lane];
        int4 r1 = xin[(size_t)s1 * DIMH4 + lane];
        int4 r2 = xin[(size_t)s2 * DIMH4 + lane];
        int4 r3 = xin[(size_t)s3 * DIMH4 + lane];
        acc.add(r0);
        acc.add(r1);
        acc.add(r2);
        acc.add(r3);
    }
    for (; e < end; e++) {
        int s = g_csrsrc[e];
        int4 r = xin[(size_t)s * DIMH4 + lane];
        acc.add(r);
    }
}

// ---------------- graph preprocessing ----------------
__global__ void k_zero_deg() {
    int i = blockIdx.x * blockDim.x + threadIdx.x;
    if (i < N_NODES) { g_deg[i] = 0; g_need2[i] = 0; }
}

__global__ void k_count_deg(const int* __restrict__ erow, const int* __restrict__ ecol) {
    int e = blockIdx.x * blockDim.x + threadIdx.x;
    if (e < N_EDGES) {
        atomicAdd(&g_deg[erow[e]], 1);
        atomicAdd(&g_deg[N_USERS + ecol[e]], 1);
    }
}

__global__ void k_scan1() {
    __shared__ int s[SCAN_BLK];
    int tid = threadIdx.x;
    int i = blockIdx.x * SCAN_BLK + tid;
    int v = (i < N_NODES) ? g_deg[i] : 0;
    s[tid] = v;
    __syncthreads();
    for (int off = 1; off < SCAN_BLK; off <<= 1) {
        int t = (tid >= off) ? s[tid - off] : 0;
        __syncthreads();
        s[tid] += t;
        __syncthreads();
    }
    if (i < N_NODES) g_rowptr[i] = s[tid] - v;
    if (tid == SCAN_BLK - 1) g_part[blockIdx.x] = s[tid];
}

__global__ void k_scan2() {
    __shared__ int s[512];
    int tid = threadIdx.x;
    int v = (tid < SCAN_NB) ? g_part[tid] : 0;
    s[tid] = v;
    __syncthreads();
    for (int off = 1; off < 512; off <<= 1) {
        int t = (tid >= off) ? s[tid - off] : 0;
        __syncthreads();
        s[tid] += t;
        __syncthreads();
    }
    if (tid < SCAN_NB) g_part[tid] = s[tid] - v;
}

__global__ void k_scan3() {
    int i = blockIdx.x * blockDim.x + threadIdx.x;
    if (i < N_NODES) {
        int rp = g_rowptr[i] + g_part[i / SCAN_BLK];
        g_rowptr[i] = rp;
        g_cursor[i] = rp;
        int d = g_deg[i];
        float df = (float)(d < 1 ? 1 : d);
        g_dinv[i] = rsqrtf(df);
        g_rdeg[i] = sqrtf(df);
    }
    if (i == 0) g_rowptr[N_NODES] = NDIR;
}

// ---------------- fused: CSR scatter (latency-bound) || p0 init (BW-bound) ------------
// first SCATTER_BLOCKS blocks do the edge scatter; the rest convert embeddings to fp16.
__global__ void __launch_bounds__(256) k_scatter_init(
        const int* __restrict__ erow, const int* __restrict__ ecol,
        const float* __restrict__ uemb, const float* __restrict__ iemb) {
    if (blockIdx.x < SCATTER_BLOCKS) {
        int e = blockIdx.x * 256 + threadIdx.x;
        if (e < N_EDGES) {
            int u = erow[e];
            int it = N_USERS + ecol[e];
            int p = atomicAdd(&g_cursor[u], 1);
            g_csrsrc[p] = it;
            int q = atomicAdd(&g_cursor[it], 1);
            g_csrsrc[q] = u;
        }
    } else {
        size_t i = (size_t)(blockIdx.x - SCATTER_BLOCKS) * 256 + threadIdx.x;  // half2 idx
        if (i >= INIT_H2) return;
        size_t ei = i * 2;
        size_t row = ei >> 8;
        float d = g_dinv[row];
        float2 v;
        if (ei < (size_t)N_USERS * DIM) v = ((const float2*)uemb)[i];
        else v = ((const float2*)iemb)[i - (size_t)N_USERS * DIM / 2];
        __stcs((__half2*)g_p0 + i, __floats2half2_rn(v.x * d, v.y * d));
    }
}

// ---------------- mark rows whose p2 is needed: batch nodes + their neighbors ----------
__global__ void k_mark(const int* __restrict__ uidx, const int* __restrict__ pidx,
                       const int* __restrict__ nidx) {
    int j = blockIdx.x * 8 + (threadIdx.x >> 5);
    int lane = threadIdx.x & 31;
    if (j >= 3 * BATCH) return;
    int node;
    if (j < BATCH) node = uidx[j];
    else if (j < 2 * BATCH) node = N_USERS + pidx[j - BATCH];
    else node = N_USERS + nidx[j - 2 * BATCH];
    if (lane == 0) g_need2[node] = 1;
    int beg = g_rowptr[node];
    int end = g_rowptr[node + 1];
    for (int e = beg + lane; e < end; e += 32) {
        g_need2[g_csrsrc[e]] = 1;
    }
}

// ---------------- full propagation: p_out[dst] = half(dinv[dst]^2 * sum_src p_in[src]) --
// warp per dst row; lane handles 8 halves (one int4); fp32 accumulation; streaming store.
__global__ void __launch_bounds__(256) k_spmm_full(int which, int use_flag) {
    const int4* __restrict__ xin = (const int4*)(which == 0 ? g_p0 : g_p1);
    int4* __restrict__ xout = (int4*)(which == 0 ? g_p1 : g_p2);

    int row = blockIdx.x * 8 + (threadIdx.x >> 5);
    int lane = threadIdx.x & 31;
    if (row >= N_NODES) return;
    if (use_flag && !g_need2[row]) return;

    int beg = g_rowptr[row];
    int end = g_rowptr[row + 1];
    float di = g_dinv[row];
    float w = di * di;

    Acc8 acc;
    acc.init();
    gather_sum(xin, beg, end, lane, acc);

    int4 out;
    __half2 o0 = __floats2half2_rn(acc.a0 * w, acc.a1 * w);
    __half2 o1 = __floats2half2_rn(acc.a2 * w, acc.a3 * w);
    __half2 o2 = __floats2half2_rn(acc.a4 * w, acc.a5 * w);
    __half2 o3 = __floats2half2_rn(acc.a6 * w, acc.a7 * w);
    out.x = *(int*)&o0; out.y = *(int*)&o1; out.z = *(int*)&o2; out.w = *(int*)&o3;
    __stcs(&xout[(size_t)row * DIMH4 + lane], out);
}

// ---------------- fused finalize ----------------
__device__ __forceinline__ void load8h(const int4* base, size_t row, int lane, float* f) {
    int4 raw = base[row * DIMH4 + lane];
    float2 f0 = __half22float2(*(__half2*)&raw.x);
    float2 f1 = __half22float2(*(__half2*)&raw.y);
    float2 f2 = __half22float2(*(__half2*)&raw.z);
    float2 f3 = __half22float2(*(__half2*)&raw.w);
    f[0] = f0.x; f[1] = f0.y; f[2] = f1.x; f[3] = f1.y;
    f[4] = f2.x; f[5] = f2.y; f[6] = f3.x; f[7] = f3.y;
}

// compute acc[0..8) for node; also writes raw embedding row to rawout
__device__ __forceinline__ void node_acc(int node, const float4* __restrict__ emb4,
                                         size_t embrow, int lane,
                                         float* accv, float4* __restrict__ rawout) {
    const int4* p1h = (const int4*)g_p1;
    const int4* p2h = (const int4*)g_p2;

    int beg = g_rowptr[node];
    int end = g_rowptr[node + 1];
    float di = g_dinv[node];
    float rd = g_rdeg[node];

    // x3 gather over neighbors' p2 (4x-unrolled)
    Acc8 acc;
    acc.init();
    gather_sum(p2h, beg, end, lane, acc);
    float x3[8] = {acc.a0 * di, acc.a1 * di, acc.a2 * di, acc.a3 * di,
                   acc.a4 * di, acc.a5 * di, acc.a6 * di, acc.a7 * di};

    float4 e0 = emb4[embrow * DIM4 + lane * 2];
    float4 e1 = emb4[embrow * DIM4 + lane * 2 + 1];
    float e[8] = {e0.x, e0.y, e0.z, e0.w, e1.x, e1.y, e1.z, e1.w};

    float t1[8], t2[8];
    load8h(p1h, (size_t)node, lane, t1);
    load8h(p2h, (size_t)node, lane, t2);
#pragma unroll
    for (int k = 0; k < 8; k++) accv[k] = e[k] + (t1[k] + t2[k]) * rd + x3[k];

    __stcs(&rawout[lane * 2], e0);
    __stcs(&rawout[lane * 2 + 1], e1);
}

__global__ void __launch_bounds__(256) k_finalize(
        const int* __restrict__ uidx, const int* __restrict__ pidx,
        const int* __restrict__ nidx,
        const float* __restrict__ uemb, const float* __restrict__ iemb,
        float* __restrict__ out) {
    int b = blockIdx.x * 8 + (threadIdx.x >> 5);
    int lane = threadIdx.x & 31;
    if (b >= BATCH) return;

    int u = uidx[b];
    int pi = pidx[b];
    int ni = nidx[b];

    float4* oue = (float4*)(out + 2 * BATCH) + (size_t)b * DIM4;
    float4* ope = (float4*)(out + 2 * BATCH + (size_t)BATCH * DIM) + (size_t)b * DIM4;
    float4* one_ = (float4*)(out + 2 * BATCH + (size_t)2 * BATCH * DIM) + (size_t)b * DIM4;

    float au[8], ap[8], an[8];
    node_acc(u, (const float4*)uemb, (size_t)u, lane, au, oue);
    node_acc(N_USERS + pi, (const float4*)iemb, (size_t)pi, lane, ap, ope);
    node_acc(N_USERS + ni, (const float4*)iemb, (size_t)ni, lane, an, one_);

    float ps = 0.f, ns = 0.f;
#pragma unroll
    for (int k = 0; k < 8; k++) {
        ps += au[k] * ap[k];
        ns += au[k] * an[k];
    }
#pragma unroll
    for (int off = 16; off > 0; off >>= 1) {
        ps += __shfl_down_sync(0xFFFFFFFFu, ps, off);
        ns += __shfl_down_sync(0xFFFFFFFFu, ns, off);
    }
    const float inv16 = 1.0f / 16.0f;   // (1/(N_LAYERS+1))^2
    if (lane == 0) {
        out[b] = ps * inv16;
        out[BATCH + b] = ns * inv16;
    }
}

// ---------------- launch ----------------
extern "C" void kernel_launch(void* const* d_in, const int* in_sizes, int n_in,
                              void* d_out, int out_size) {
    const float* user_emb = (const float*)d_in[0];
    const float* item_emb = (const float*)d_in[1];
    const int* edge_row = (const int*)d_in[2];
    const int* edge_col = (const int*)d_in[3];
    const int* users_idx = (const int*)d_in[4];
    const int* pos_idx = (const int*)d_in[5];
    const int* neg_idx = (const int*)d_in[6];
    float* out = (float*)d_out;

    // graph build
    k_zero_deg<<<(N_NODES + 255) / 256, 256>>>();
    k_count_deg<<<(N_EDGES + 255) / 256, 256>>>(edge_row, edge_col);
    k_scan1<<<SCAN_NB, SCAN_BLK>>>();
    k_scan2<<<1, 512>>>();
    k_scan3<<<(N_NODES + 255) / 256, 256>>>();

    // fused: CSR scatter || p0 = half(dinv * x0)
    k_scatter_init<<<SCATTER_BLOCKS + INIT_BLOCKS, 256>>>(edge_row, edge_col,
                                                          user_emb, item_emb);

    // mark rows needed in layer 2 (batch nodes + 1-hop neighbors)
    k_mark<<<(3 * BATCH + 7) / 8, 256>>>(users_idx, pos_idx, neg_idx);

    // layer 1 full; layer 2 only at marked rows
    int spmm_blocks = (N_NODES + 7) / 8;
    k_spmm_full<<<spmm_blocks, 256>>>(0, 0);   // p0 -> p1 (all rows)
    k_spmm_full<<<spmm_blocks, 256>>>(1, 1);   // p1 -> p2 (marked rows only)

    // fused sparse layer 3 + outputs
    k_finalize<<<BATCH / 8, 256>>>(users_idx, pos_idx, neg_idx, user_emb, item_emb, out);
}

// round 8
// speedup vs baseline: 3.6203x; 1.0146x over previous
#include <cuda_runtime.h>
#include <cuda_fp16.h>

#define N_USERS 100000
#define N_ITEMS 200000
#define N_NODES (N_USERS + N_ITEMS)
#define DIM 256
#define DIM4 (DIM / 4)
#define DIMH4 (DIM / 8)     // int4 (8 halves) per row = 32
#define N_EDGES 1000000
#define NDIR (2 * N_EDGES)
#define BATCH 8192
#define SCAN_BLK 1024
#define SCAN_NB ((N_NODES + SCAN_BLK - 1) / SCAN_BLK)   // 293
#define SCATTER_BLOCKS ((N_EDGES + 255) / 256)          // 3907
#define INIT_H2 ((size_t)N_NODES * DIM / 2)             // 38.4M half2
#define INIT_BLOCKS ((int)((INIT_H2 + 255) / 256))
#define ZERO_BLOCKS ((N_NODES + 255) / 256)             // 1172
#define MARKB_BLOCKS ((3 * BATCH + 255) / 256)          // 96

// ---------------- device scratch (static: allowed) ----------------
// propagating buffers store p_l = dinv * x_l  (pre-scaled), fp16
__device__ __half g_p0[(size_t)N_NODES * DIM];   // 154 MB
__device__ __half g_p1[(size_t)N_NODES * DIM];   // 154 MB
__device__ __half g_p2[(size_t)N_NODES * DIM];   // 154 MB
__device__ int   g_deg[N_NODES];
__device__ int   g_rowptr[N_NODES + 1];
__device__ int   g_cursor[N_NODES];
__device__ float g_dinv[N_NODES];                // deg^-1/2
__device__ float g_rdeg[N_NODES];                // deg^+1/2 (un-scale factor)
__device__ int   g_csrsrc[NDIR];                 // 8 MB
__device__ int   g_part[SCAN_NB];
// write-once idempotent flags (same batch every call -> identical fixed point)
__device__ unsigned char g_need_b[N_NODES];      // node is a batch node
__device__ unsigned char g_need2[N_NODES];       // p2 needed: batch + 1-hop

// ---------------- accumulator helpers ----------------
struct Acc8 {
    float a0, a1, a2, a3, a4, a5, a6, a7;
    __device__ __forceinline__ void init() {
        a0 = a1 = a2 = a3 = a4 = a5 = a6 = a7 = 0.f;
    }
    __device__ __forceinline__ void add(const int4& raw) {
        float2 f0 = __half22float2(*(__half2*)&raw.x);
        float2 f1 = __half22float2(*(__half2*)&raw.y);
        float2 f2 = __half22float2(*(__half2*)&raw.z);
        float2 f3 = __half22float2(*(__half2*)&raw.w);
        a0 += f0.x; a1 += f0.y; a2 += f1.x; a3 += f1.y;
        a4 += f2.x; a5 += f2.y; a6 += f3.x; a7 += f3.y;
    }
};

// gather-sum over adjacency [beg,end) from fp16 buffer, 4x unrolled for MLP
__device__ __forceinline__ void gather_sum(const int4* __restrict__ xin, int beg, int end,
                                           int lane, Acc8& acc) {
    int e = beg;
    for (; e + 4 <= end; e += 4) {
        int s0 = g_csrsrc[e];
        int s1 = g_csrsrc[e + 1];
        int s2 = g_csrsrc[e + 2];
        int s3 = g_csrsrc[e + 3];
        int4 r0 = xin[(size_t)s0 * DIMH4 + lane];
        int4 r1 = xin[(size_t)s1 * DIMH4 + lane];
        int4 r2 = xin[(size_t)s2 * DIMH4 + lane];
        int4 r3 = xin[(size_t)s3 * DIMH4 + lane];
        acc.add(r0);
        acc.add(r1);
        acc.add(r2);
        acc.add(r3);
    }
    for (; e < end; e++) {
        int s = g_csrsrc[e];
        int4 r = xin[(size_t)s * DIMH4 + lane];
        acc.add(r);
    }
}

// ---------------- 1: zero degrees + mark batch nodes (disjoint block ranges) ----------
__global__ void k_zero_mark(const int* __restrict__ uidx, const int* __restrict__ pidx,
                            const int* __restrict__ nidx) {
    if (blockIdx.x < ZERO_BLOCKS) {
        int i = blockIdx.x * 256 + threadIdx.x;
        if (i < N_NODES) g_deg[i] = 0;
    } else {
        int j = (blockIdx.x - ZERO_BLOCKS) * 256 + threadIdx.x;
        if (j < 3 * BATCH) {
            int node;
            if (j < BATCH) node = uidx[j];
            else if (j < 2 * BATCH) node = N_USERS + pidx[j - BATCH];
            else node = N_USERS + nidx[j - 2 * BATCH];
            g_need_b[node] = 1;   // idempotent
            g_need2[node] = 1;    // batch nodes need p2 themselves
        }
    }
}

// ---------------- 2: count degrees + mark 1-hop neighbors of batch nodes --------------
__global__ void k_count_mark(const int* __restrict__ erow, const int* __restrict__ ecol) {
    int e = blockIdx.x * blockDim.x + threadIdx.x;
    if (e < N_EDGES) {
        int u = erow[e];
        int it = N_USERS + ecol[e];
        atomicAdd(&g_deg[u], 1);
        atomicAdd(&g_deg[it], 1);
        if (g_need_b[u]) g_need2[it] = 1;   // idempotent byte stores
        if (g_need_b[it]) g_need2[u] = 1;
    }
}

// ---------------- 3: per-block scan (within-block exclusive + block totals) -----------
__global__ void k_scan1() {
    __shared__ int s[SCAN_BLK];
    int tid = threadIdx.x;
    int i = blockIdx.x * SCAN_BLK + tid;
    int v = (i < N_NODES) ? g_deg[i] : 0;
    s[tid] = v;
    __syncthreads();
    for (int off = 1; off < SCAN_BLK; off <<= 1) {
        int t = (tid >= off) ? s[tid - off] : 0;
        __syncthreads();
        s[tid] += t;
        __syncthreads();
    }
    if (i < N_NODES) g_rowptr[i] = s[tid] - v;
    if (tid == SCAN_BLK - 1) g_part[blockIdx.x] = s[tid];
}

// ---------------- 4: finalize scan: inline partial-prefix reduce + dinv/rdeg ----------
// 256-thread blocks; all nodes of a block share one part-prefix (k = blockIdx>>2).
__global__ void __launch_bounds__(256) k_scan3() {
    __shared__ int s[256];
    int tid = threadIdx.x;
    int k = blockIdx.x >> 2;              // number of preceding SCAN_BLK partitions
    int v = 0;
    if (tid < k) v = g_part[tid];
    if (tid + 256 < k) v += g_part[tid + 256];   // k <= 293 < 512
    s[tid] = v;
    __syncthreads();
    for (int off = 128; off > 0; off >>= 1) {
        if (tid < off) s[tid] += s[tid + off];
        __syncthreads();
    }
    int prefix = s[0];

    int i = blockIdx.x * 256 + tid;
    if (i < N_NODES) {
        int rp = g_rowptr[i] + prefix;
        g_rowptr[i] = rp;
        g_cursor[i] = rp;
        int d = g_deg[i];
        float df = (float)(d < 1 ? 1 : d);
        g_dinv[i] = rsqrtf(df);
        g_rdeg[i] = sqrtf(df);
    }
    if (i == 0) g_rowptr[N_NODES] = NDIR;
}

// ---------------- 5: fused CSR scatter (latency-bound) || p0 init (BW-bound) ----------
__global__ void __launch_bounds__(256) k_scatter_init(
        const int* __restrict__ erow, const int* __restrict__ ecol,
        const float* __restrict__ uemb, const float* __restrict__ iemb) {
    if (blockIdx.x < SCATTER_BLOCKS) {
        int e = blockIdx.x * 256 + threadIdx.x;
        if (e < N_EDGES) {
            int u = erow[e];
            int it = N_USERS + ecol[e];
            int p = atomicAdd(&g_cursor[u], 1);
            g_csrsrc[p] = it;
            int q = atomicAdd(&g_cursor[it], 1);
            g_csrsrc[q] = u;
        }
    } else {
        size_t i = (size_t)(blockIdx.x - SCATTER_BLOCKS) * 256 + threadIdx.x;  // half2 idx
        if (i >= INIT_H2) return;
        size_t ei = i * 2;
        size_t row = ei >> 8;
        float d = g_dinv[row];
        float2 v;
        if (ei < (size_t)N_USERS * DIM) v = ((const float2*)uemb)[i];
        else v = ((const float2*)iemb)[i - (size_t)N_USERS * DIM / 2];
        ((__half2*)g_p0)[i] = __floats2half2_rn(v.x * d, v.y * d);
    }
}

// ---------------- 6/7: full propagation, p_out[dst] = half(dinv^2 * sum_src p_in[src]) -
__global__ void __launch_bounds__(256) k_spmm_full(int which, int use_flag) {
    const int4* __restrict__ xin = (const int4*)(which == 0 ? g_p0 : g_p1);
    int4* __restrict__ xout = (int4*)(which == 0 ? g_p1 : g_p2);

    int row = blockIdx.x * 8 + (threadIdx.x >> 5);
    int lane = threadIdx.x & 31;
    if (row >= N_NODES) return;
    if (use_flag && !g_need2[row]) return;

    int beg = g_rowptr[row];
    int end = g_rowptr[row + 1];
    float di = g_dinv[row];
    float w = di * di;

    Acc8 acc;
    acc.init();
    gather_sum(xin, beg, end, lane, acc);

    int4 out;
    __half2 o0 = __floats2half2_rn(acc.a0 * w, acc.a1 * w);
    __half2 o1 = __floats2half2_rn(acc.a2 * w, acc.a3 * w);
    __half2 o2 = __floats2half2_rn(acc.a4 * w, acc.a5 * w);
    __half2 o3 = __floats2half2_rn(acc.a6 * w, acc.a7 * w);
    out.x = *(int*)&o0; out.y = *(int*)&o1; out.z = *(int*)&o2; out.w = *(int*)&o3;
    xout[(size_t)row * DIMH4 + lane] = out;   // normal store: re-read by next kernel
}

// ---------------- 8: fused finalize ----------------
__device__ __forceinline__ void load8h(const int4* base, size_t row, int lane, float* f) {
    int4 raw = base[row * DIMH4 + lane];
    float2 f0 = __half22float2(*(__half2*)&raw.x);
    float2 f1 = __half22float2(*(__half2*)&raw.y);
    float2 f2 = __half22float2(*(__half2*)&raw.z);
    float2 f3 = __half22float2(*(__half2*)&raw.w);
    f[0] = f0.x; f[1] = f0.y; f[2] = f1.x; f[3] = f1.y;
    f[4] = f2.x; f[5] = f2.y; f[6] = f3.x; f[7] = f3.y;
}

__device__ __forceinline__ void node_acc(int node, const float4* __restrict__ emb4,
                                         size_t embrow, int lane,
                                         float* accv, float4* __restrict__ rawout) {
    const int4* p1h = (const int4*)g_p1;
    const int4* p2h = (const int4*)g_p2;

    int beg = g_rowptr[node];
    int end = g_rowptr[node + 1];
    float di = g_dinv[node];
    float rd = g_rdeg[node];

    Acc8 acc;
    acc.init();
    gather_sum(p2h, beg, end, lane, acc);
    float x3[8] = {acc.a0 * di, acc.a1 * di, acc.a2 * di, acc.a3 * di,
                   acc.a4 * di, acc.a5 * di, acc.a6 * di, acc.a7 * di};

    float4 e0 = emb4[embrow * DIM4 + lane * 2];
    float4 e1 = emb4[embrow * DIM4 + lane * 2 + 1];
    float e[8] = {e0.x, e0.y, e0.z, e0.w, e1.x, e1.y, e1.z, e1.w};

    float t1[8], t2[8];
    load8h(p1h, (size_t)node, lane, t1);
    load8h(p2h, (size_t)node, lane, t2);
#pragma unroll
    for (int k = 0; k < 8; k++) accv[k] = e[k] + (t1[k] + t2[k]) * rd + x3[k];

    __stcs(&rawout[lane * 2], e0);        // out buffer is write-only: stream it
    __stcs(&rawout[lane * 2 + 1], e1);
}

__global__ void __launch_bounds__(256) k_finalize(
        const int* __restrict__ uidx, const int* __restrict__ pidx,
        const int* __restrict__ nidx,
        const float* __restrict__ uemb, const float* __restrict__ iemb,
        float* __restrict__ out) {
    int b = blockIdx.x * 8 + (threadIdx.x >> 5);
    int lane = threadIdx.x & 31;
    if (b >= BATCH) return;

    int u = uidx[b];
    int pi = pidx[b];
    int ni = nidx[b];

    float4* oue = (float4*)(out + 2 * BATCH) + (size_t)b * DIM4;
    float4* ope = (float4*)(out + 2 * BATCH + (size_t)BATCH * DIM) + (size_t)b * DIM4;
    float4* one_ = (float4*)(out + 2 * BATCH + (size_t)2 * BATCH * DIM) + (size_t)b * DIM4;

    float au[8], ap[8], an[8];
    node_acc(u, (const float4*)uemb, (size_t)u, lane, au, oue);
    node_acc(N_USERS + pi, (const float4*)iemb, (size_t)pi, lane, ap, ope);
    node_acc(N_USERS + ni, (const float4*)iemb, (size_t)ni, lane, an, one_);

    float ps = 0.f, ns = 0.f;
#pragma unroll
    for (int k = 0; k < 8; k++) {
        ps += au[k] * ap[k];
        ns += au[k] * an[k];
    }
#pragma unroll
    for (int off = 16; off > 0; off >>= 1) {
        ps += __shfl_down_sync(0xFFFFFFFFu, ps, off);
        ns += __shfl_down_sync(0xFFFFFFFFu, ns, off);
    }
    const float inv16 = 1.0f / 16.0f;   // (1/(N_LAYERS+1))^2
    if (lane == 0) {
        out[b] = ps * inv16;
        out[BATCH + b] = ns * inv16;
    }
}

// ---------------- launch ----------------
extern "C" void kernel_launch(void* const* d_in, const int* in_sizes, int n_in,
                              void* d_out, int out_size) {
    const float* user_emb = (const float*)d_in[0];
    const float* item_emb = (const float*)d_in[1];
    const int* edge_row = (const int*)d_in[2];
    const int* edge_col = (const int*)d_in[3];
    const int* users_idx = (const int*)d_in[4];
    const int* pos_idx = (const int*)d_in[5];
    const int* neg_idx = (const int*)d_in[6];
    float* out = (float*)d_out;

    // 1: zero degrees + mark batch nodes
    k_zero_mark<<<ZERO_BLOCKS + MARKB_BLOCKS, 256>>>(users_idx, pos_idx, neg_idx);
    // 2: count degrees + mark 1-hop neighbors
    k_count_mark<<<(N_EDGES + 255) / 256, 256>>>(edge_row, edge_col);
    // 3-4: scan (block partials, then fused prefix+finalize)
    k_scan1<<<SCAN_NB, SCAN_BLK>>>();
    k_scan3<<<(N_NODES + 255) / 256, 256>>>();
    // 5: fused CSR scatter || p0 = half(dinv * x0)
    k_scatter_init<<<SCATTER_BLOCKS + INIT_BLOCKS, 256>>>(edge_row, edge_col,
                                                          user_emb, item_emb);
    // 6-7: layer 1 full; layer 2 only at marked rows
    int spmm_blocks = (N_NODES + 7) / 8;
    k_spmm_full<<<spmm_blocks, 256>>>(0, 0);   // p0 -> p1 (all rows)
    k_spmm_full<<<spmm_blocks, 256>>>(1, 1);   // p1 -> p2 (marked rows only)
    // 8: fused sparse layer 3 + outputs
    k_finalize<<<BATCH / 8, 256>>>(users_idx, pos_idx, neg_idx, user_emb, item_emb, out);
}